// round 7
// baseline (speedup 1.0000x reference)
#include <cuda_runtime.h>
#include <cuda_bf16.h>
#include <cstdint>

#define NN 100000
#define DD 128
#define HH 64
#define KK 8
#define LL 3
#define CC 16
#define EE 1600000

// ---------------- device scratch ----------------
__device__ __align__(128) float g_ha[NN * HH];
__device__ __align__(128) float g_hb[NN * HH];
__device__ __align__(128) float g_dn[NN];
__device__ __align__(128) int   g_deg[NN];
__device__ __align__(128) int   g_ptr[NN + 1];
__device__ __align__(128) int   g_cur[NN];
__device__ __align__(128) int   g_bsum[128];
__device__ __align__(128) uint2 g_csr[EE];            // (src, val bits)
// pre-packed B fragments: conv [48 images], fc0 [2 images]
__device__ __align__(128) uint2 g_wpack[48 * 2048];
__device__ __align__(128) uint2 g_wpack0[2 * 2048];

// single dynamic smem symbol shared by all kernels
extern __shared__ unsigned char dyn_smem[];

__device__ __forceinline__ uint16_t bf16_bits(float v) {
    __nv_bfloat16 b = __float2bfloat16(v);
    return *reinterpret_cast<uint16_t*>(&b);
}
__device__ __forceinline__ float bf16_val(float v) {
    return __bfloat162float(__float2bfloat16(v));
}
__device__ __forceinline__ uint32_t pack2(uint16_t lo, uint16_t hi) {
    return (uint32_t)lo | ((uint32_t)hi << 16);
}

// mma.sync m16n8k16 bf16 (row.col), f32 accumulate
__device__ __forceinline__ void hmma(float* d, const uint32_t* a, uint2 b) {
    asm volatile(
        "mma.sync.aligned.m16n8k16.row.col.f32.bf16.bf16.f32 "
        "{%0,%1,%2,%3}, {%4,%5,%6,%7}, {%8,%9}, {%0,%1,%2,%3};"
        : "+f"(d[0]), "+f"(d[1]), "+f"(d[2]), "+f"(d[3])
        : "r"(a[0]), "r"(a[1]), "r"(a[2]), "r"(a[3]), "r"(b.x), "r"(b.y));
}

// ---------------- CSR build kernels ----------------
__global__ void zero_deg_kernel() {
    int i = blockIdx.x * blockDim.x + threadIdx.x;
    if (i < NN) g_deg[i] = 0;
}
__global__ void deg_kernel(const int* __restrict__ col) {
    int e = blockIdx.x * blockDim.x + threadIdx.x;
    if (e < EE) atomicAdd(&g_deg[col[e]], 1);
}
__global__ void dn_kernel() {
    int i = blockIdx.x * blockDim.x + threadIdx.x;
    if (i < NN) {
        int d = g_deg[i];
        g_dn[i] = d > 0 ? rsqrtf((float)d) : 0.f;
    }
}
__global__ void __launch_bounds__(1024) scan_block_kernel() {
    __shared__ int s[1024];
    int t = threadIdx.x;
    int i = blockIdx.x * 1024 + t;
    int v = (i < NN) ? g_deg[i] : 0;
    s[t] = v;
    __syncthreads();
#pragma unroll
    for (int off = 1; off < 1024; off <<= 1) {
        int x = (t >= off) ? s[t - off] : 0;
        __syncthreads();
        s[t] += x;
        __syncthreads();
    }
    if (i < NN) g_ptr[i] = s[t] - v;  // exclusive within block
    if (t == 1023) g_bsum[blockIdx.x] = s[1023];
}
__global__ void scan_bsum_kernel(int nblocks) {
    if (threadIdx.x == 0 && blockIdx.x == 0) {
        int acc = 0;
        for (int b = 0; b < nblocks; b++) {
            int v = g_bsum[b];
            g_bsum[b] = acc;
            acc += v;
        }
        g_ptr[NN] = acc;
    }
}
__global__ void __launch_bounds__(1024) scan_add_kernel() {
    int i = blockIdx.x * 1024 + threadIdx.x;
    if (i < NN) {
        int p = g_ptr[i] + g_bsum[blockIdx.x];
        g_ptr[i] = p;
        g_cur[i] = p;
    }
}
__global__ void fill_csr_kernel(const int* __restrict__ row, const int* __restrict__ col) {
    int e = blockIdx.x * blockDim.x + threadIdx.x;
    if (e < EE) {
        int c = col[e], r = row[e];
        int p = atomicAdd(&g_cur[c], 1);
        g_csr[p] = make_uint2((unsigned)r, __float_as_uint(g_dn[r] * g_dn[c]));
    }
}

// ---------------- W prepack: bf16 hi/lo split, HMMA B-fragment order ----------------
__device__ __forceinline__ void wpack_img(const float* __restrict__ w, uint2* __restrict__ dst, int sel) {
    for (int i = threadIdx.x; i < 2048; i += 256) {
        int lane = i & 31;
        int nt = (i >> 5) & 7;
        int ks = i >> 8;
        int tig = lane & 3, gid = lane >> 2;
        int n = nt * 8 + gid;
        int k0 = ks * 16 + tig * 2;
        float v0 = w[(k0 + 0) * 64 + n];
        float v1 = w[(k0 + 1) * 64 + n];
        float v2 = w[(k0 + 8) * 64 + n];
        float v3 = w[(k0 + 9) * 64 + n];
        uint16_t h0, h1, h2, h3;
        if (sel == 0) {
            h0 = bf16_bits(v0); h1 = bf16_bits(v1); h2 = bf16_bits(v2); h3 = bf16_bits(v3);
        } else {
            h0 = bf16_bits(v0 - bf16_val(v0));
            h1 = bf16_bits(v1 - bf16_val(v1));
            h2 = bf16_bits(v2 - bf16_val(v2));
            h3 = bf16_bits(v3 - bf16_val(v3));
        }
        dst[i] = make_uint2(pack2(h0, h1), pack2(h2, h3));
    }
}
__global__ void wpack_kernel(const float* __restrict__ cw) {
    int img = blockIdx.x;          // 0..47
    wpack_img(cw + (img >> 1) * 8192, g_wpack + img * 2048, img & 1);
}
__global__ void wpack0_kernel(const float* __restrict__ w0) {
    wpack_img(w0, g_wpack0 + blockIdx.x * 2048, blockIdx.x);
}

// ---------------- fc0 via HMMA: h = relu(x @ w + b) ----------------
#define A_STRIDE 136
#define SM_AH 0
#define SM_AL (128 * A_STRIDE * 2)
#define SM_E  (2 * 128 * A_STRIDE * 2)
#define SM_EW (SM_E + 128 * 8 * 4)
#define CONV_SMEM (SM_EW + 520 * 4)
#define FC0_SMEM  (2 * 128 * A_STRIDE * 2)

__global__ void __launch_bounds__(256, 1) fc0_mma_kernel(const float* __restrict__ x,
                                                         const float* __restrict__ bias) {
    unsigned char* smb = dyn_smem;
    uint16_t* Ah = reinterpret_cast<uint16_t*>(smb + SM_AH);
    uint16_t* Al = reinterpret_cast<uint16_t*>(smb + SM_AL);

    int t = threadIdx.x;
    int wid = t >> 5, lane = t & 31;
    int tig = lane & 3, gid = lane >> 2;
    int n0 = blockIdx.x * 128;

    const float4* x4 = reinterpret_cast<const float4*>(x);
    for (int idx = t; idx < 4096; idx += 256) {
        int r = idx >> 5, j = idx & 31;
        int gn = n0 + r;
        float4 v = make_float4(0.f, 0.f, 0.f, 0.f);
        if (gn < NN) v = x4[gn * 32 + j];
        uint16_t hx = bf16_bits(v.x), hy = bf16_bits(v.y);
        uint16_t hz = bf16_bits(v.z), hw = bf16_bits(v.w);
        uint16_t lx = bf16_bits(v.x - bf16_val(v.x));
        uint16_t ly = bf16_bits(v.y - bf16_val(v.y));
        uint16_t lz = bf16_bits(v.z - bf16_val(v.z));
        uint16_t lw = bf16_bits(v.w - bf16_val(v.w));
        *reinterpret_cast<uint2*>(&Ah[r * A_STRIDE + j * 4]) = make_uint2(pack2(hx, hy), pack2(hz, hw));
        *reinterpret_cast<uint2*>(&Al[r * A_STRIDE + j * 4]) = make_uint2(pack2(lx, ly), pack2(lz, lw));
    }
    __syncthreads();

    // A fragments (own warp's rows)
    uint32_t ah[8][4], al[8][4];
    int fr0 = wid * 16 + gid;
#pragma unroll
    for (int s = 0; s < 8; s++) {
        int kc = s * 16 + tig * 2;
        ah[s][0] = *reinterpret_cast<const uint32_t*>(&Ah[fr0 * A_STRIDE + kc]);
        ah[s][1] = *reinterpret_cast<const uint32_t*>(&Ah[(fr0 + 8) * A_STRIDE + kc]);
        ah[s][2] = *reinterpret_cast<const uint32_t*>(&Ah[fr0 * A_STRIDE + kc + 8]);
        ah[s][3] = *reinterpret_cast<const uint32_t*>(&Ah[(fr0 + 8) * A_STRIDE + kc + 8]);
        al[s][0] = *reinterpret_cast<const uint32_t*>(&Al[fr0 * A_STRIDE + kc]);
        al[s][1] = *reinterpret_cast<const uint32_t*>(&Al[(fr0 + 8) * A_STRIDE + kc]);
        al[s][2] = *reinterpret_cast<const uint32_t*>(&Al[fr0 * A_STRIDE + kc + 8]);
        al[s][3] = *reinterpret_cast<const uint32_t*>(&Al[(fr0 + 8) * A_STRIDE + kc + 8]);
    }

    float acc[8][4];
#pragma unroll
    for (int nt = 0; nt < 8; nt++)
#pragma unroll
        for (int i = 0; i < 4; i++) acc[nt][i] = 0.f;

    const uint2* bh = g_wpack0;
    const uint2* bl = g_wpack0 + 2048;
#pragma unroll
    for (int s = 0; s < 8; s++) {
        uint2 b[8];
#pragma unroll
        for (int nt = 0; nt < 8; nt++) b[nt] = bh[(s * 8 + nt) * 32 + lane];
#pragma unroll
        for (int nt = 0; nt < 8; nt++) hmma(acc[nt], ah[s], b[nt]);
#pragma unroll
        for (int nt = 0; nt < 8; nt++) hmma(acc[nt], al[s], b[nt]);
    }
#pragma unroll
    for (int s = 0; s < 8; s++) {
        uint2 b[8];
#pragma unroll
        for (int nt = 0; nt < 8; nt++) b[nt] = bl[(s * 8 + nt) * 32 + lane];
#pragma unroll
        for (int nt = 0; nt < 8; nt++) hmma(acc[nt], ah[s], b[nt]);
    }

    int gn0 = n0 + wid * 16 + gid;
    int gn1 = gn0 + 8;
#pragma unroll
    for (int nt = 0; nt < 8; nt++) {
        int c = nt * 8 + tig * 2;
        float2 bi = *reinterpret_cast<const float2*>(&bias[c]);
        if (gn0 < NN) {
            float2 o;
            o.x = fmaxf(acc[nt][0] + bi.x, 0.f);
            o.y = fmaxf(acc[nt][1] + bi.y, 0.f);
            *reinterpret_cast<float2*>(&g_ha[gn0 * 64 + c]) = o;
        }
        if (gn1 < NN) {
            float2 o;
            o.x = fmaxf(acc[nt][2] + bi.x, 0.f);
            o.y = fmaxf(acc[nt][3] + bi.y, 0.f);
            *reinterpret_cast<float2*>(&g_ha[gn1 * 64 + c]) = o;
        }
    }
}

// ---------------- conv layer: fused CSR gather + gating + mma.sync bf16x3 ----------------
// Double-buffered: reads h_in everywhere, writes h_out. No in-place update -> no race.
__global__ void __launch_bounds__(256, 1) conv_mma_kernel(const float* __restrict__ h_in,
                                                          float* __restrict__ h_out,
                                                          const float* __restrict__ ew,
                                                          const float* __restrict__ eb,
                                                          int layer) {
    unsigned char* smb = dyn_smem;
    uint16_t* Ah = reinterpret_cast<uint16_t*>(smb + SM_AH);
    uint16_t* Al = reinterpret_cast<uint16_t*>(smb + SM_AL);
    uint32_t* Ah32 = reinterpret_cast<uint32_t*>(Ah);
    uint32_t* Al32 = reinterpret_cast<uint32_t*>(Al);
    float* s_e = reinterpret_cast<float*>(smb + SM_E);
    float* s_ew = reinterpret_cast<float*>(smb + SM_EW);

    int t = threadIdx.x;
    int wid = t >> 5, lane = t & 31;
    int tig = lane & 3, gid = lane >> 2;
    int n0 = blockIdx.x * 128;

    // env weights + bias into smem
    for (int i = t; i < 520; i += 256) s_ew[i] = (i < 512) ? ew[i] : eb[i - 512];

    // ---- fused gather: warp wid builds rows wid*16..wid*16+15 of A tile ----
    // cols 0..63  = gcn gather (CSR), cols 64..127 = h row; bf16 hi/lo split
    const float2* h2 = reinterpret_cast<const float2*>(h_in);
    const int RS = A_STRIDE / 2;   // row stride in uint32 (=68)
    for (int i = 0; i < 16; i++) {
        int r = (wid << 4) + i;
        int gn = n0 + r;
        float2 acc2 = make_float2(0.f, 0.f);
        float2 hv = make_float2(0.f, 0.f);
        if (gn < NN) {
            int js = g_ptr[gn], je = g_ptr[gn + 1];
            int j = js;
            for (; j + 4 <= je; j += 4) {
                uint2 c0 = g_csr[j], c1 = g_csr[j + 1], c2 = g_csr[j + 2], c3 = g_csr[j + 3];
                float2 a0 = h2[c0.x * 32 + lane];
                float2 a1 = h2[c1.x * 32 + lane];
                float2 a2 = h2[c2.x * 32 + lane];
                float2 a3 = h2[c3.x * 32 + lane];
                float v0 = __uint_as_float(c0.y), v1 = __uint_as_float(c1.y);
                float v2 = __uint_as_float(c2.y), v3 = __uint_as_float(c3.y);
                acc2.x += v0 * a0.x; acc2.y += v0 * a0.y;
                acc2.x += v1 * a1.x; acc2.y += v1 * a1.y;
                acc2.x += v2 * a2.x; acc2.y += v2 * a2.y;
                acc2.x += v3 * a3.x; acc2.y += v3 * a3.y;
            }
            for (; j < je; j++) {
                uint2 c = g_csr[j];
                float2 a = h2[c.x * 32 + lane];
                float v = __uint_as_float(c.y);
                acc2.x += v * a.x; acc2.y += v * a.y;
            }
            hv = h2[gn * 32 + lane];
        }
        Ah32[r * RS + lane] = pack2(bf16_bits(acc2.x), bf16_bits(acc2.y));
        Al32[r * RS + lane] = pack2(bf16_bits(acc2.x - bf16_val(acc2.x)),
                                    bf16_bits(acc2.y - bf16_val(acc2.y)));
        Ah32[r * RS + 32 + lane] = pack2(bf16_bits(hv.x), bf16_bits(hv.y));
        Al32[r * RS + 32 + lane] = pack2(bf16_bits(hv.x - bf16_val(hv.x)),
                                         bf16_bits(hv.y - bf16_val(hv.y)));
    }
    __syncthreads();

    // ---- A fragments into registers (own warp's rows) ----
    uint32_t ah[8][4], al[8][4];
    int fr0 = wid * 16 + gid;
#pragma unroll
    for (int s = 0; s < 8; s++) {
        int kc = s * 16 + tig * 2;
        ah[s][0] = *reinterpret_cast<const uint32_t*>(&Ah[fr0 * A_STRIDE + kc]);
        ah[s][1] = *reinterpret_cast<const uint32_t*>(&Ah[(fr0 + 8) * A_STRIDE + kc]);
        ah[s][2] = *reinterpret_cast<const uint32_t*>(&Ah[fr0 * A_STRIDE + kc + 8]);
        ah[s][3] = *reinterpret_cast<const uint32_t*>(&Ah[(fr0 + 8) * A_STRIDE + kc + 8]);
        al[s][0] = *reinterpret_cast<const uint32_t*>(&Al[fr0 * A_STRIDE + kc]);
        al[s][1] = *reinterpret_cast<const uint32_t*>(&Al[(fr0 + 8) * A_STRIDE + kc]);
        al[s][2] = *reinterpret_cast<const uint32_t*>(&Al[fr0 * A_STRIDE + kc + 8]);
        al[s][3] = *reinterpret_cast<const uint32_t*>(&Al[(fr0 + 8) * A_STRIDE + kc + 8]);
    }

    // ---- gating (threads 0..127, one node each), fp32 ----
    const float4* h4 = reinterpret_cast<const float4*>(h_in);
    if (t < 128) {
        int gn = n0 + t;
        float hrow[64];
        if (gn < NN) {
#pragma unroll
            for (int i = 0; i < 16; i++) {
                float4 v = h4[gn * 16 + i];
                hrow[4 * i] = v.x; hrow[4 * i + 1] = v.y;
                hrow[4 * i + 2] = v.z; hrow[4 * i + 3] = v.w;
            }
        } else {
#pragma unroll
            for (int i = 0; i < 64; i++) hrow[i] = 0.f;
        }
        float lg[8];
#pragma unroll
        for (int k = 0; k < 8; k++) lg[k] = s_ew[512 + k];
#pragma unroll 8
        for (int f = 0; f < 64; f++) {
            float hv = hrow[f];
            float4 w0 = *reinterpret_cast<const float4*>(&s_ew[f * 8]);
            float4 w1 = *reinterpret_cast<const float4*>(&s_ew[f * 8 + 4]);
            lg[0] += hv * w0.x; lg[1] += hv * w0.y; lg[2] += hv * w0.z; lg[3] += hv * w0.w;
            lg[4] += hv * w1.x; lg[5] += hv * w1.y; lg[6] += hv * w1.z; lg[7] += hv * w1.w;
        }
        float m = -1e30f;
#pragma unroll
        for (int k = 0; k < 8; k++) m = fmaxf(m, lg[k]);
        float sum = 0.f;
#pragma unroll
        for (int k = 0; k < 8; k++) { lg[k] = expf(lg[k] - m); sum += lg[k]; }
        float inv = 1.f / sum;
#pragma unroll
        for (int k = 0; k < 8; k++) {
            float pi = lg[k] * inv;
            s_e[t * 8 + k] = (pi > 0.1f) ? pi : 0.f;
        }
    }
    __syncthreads();

    // ---- main MMA loop over 8 heads ----
    float acc[8][4];
#pragma unroll
    for (int nt = 0; nt < 8; nt++)
#pragma unroll
        for (int i = 0; i < 4; i++) acc[nt][i] = 0.f;

    const uint2* wp = g_wpack + (layer * 8) * 2 * 2048;

#pragma unroll 1
    for (int k = 0; k < 8; k++) {
        const uint2* bh = wp + (k * 2 + 0) * 2048;
        const uint2* bl = wp + (k * 2 + 1) * 2048;
        float acck[8][4];
#pragma unroll
        for (int nt = 0; nt < 8; nt++)
#pragma unroll
            for (int i = 0; i < 4; i++) acck[nt][i] = 0.f;

        // pass 1: (Ah + Al) x Bh
#pragma unroll
        for (int s = 0; s < 8; s++) {
            uint2 b[8];
#pragma unroll
            for (int nt = 0; nt < 8; nt++) b[nt] = bh[(s * 8 + nt) * 32 + lane];
#pragma unroll
            for (int nt = 0; nt < 8; nt++) hmma(acck[nt], ah[s], b[nt]);
#pragma unroll
            for (int nt = 0; nt < 8; nt++) hmma(acck[nt], al[s], b[nt]);
        }
        // pass 2: Ah x Bl
#pragma unroll
        for (int s = 0; s < 8; s++) {
            uint2 b[8];
#pragma unroll
            for (int nt = 0; nt < 8; nt++) b[nt] = bl[(s * 8 + nt) * 32 + lane];
#pragma unroll
            for (int nt = 0; nt < 8; nt++) hmma(acck[nt], ah[s], b[nt]);
        }

        float e0 = s_e[(wid * 16 + gid) * 8 + k];
        float e1 = s_e[(wid * 16 + gid + 8) * 8 + k];
#pragma unroll
        for (int nt = 0; nt < 8; nt++) {
            acc[nt][0] += e0 * acck[nt][0];
            acc[nt][1] += e0 * acck[nt][1];
            acc[nt][2] += e1 * acck[nt][2];
            acc[nt][3] += e1 * acck[nt][3];
        }
    }

    // ---- epilogue: h_out = relu(acc + h_in) ----
    int gn0 = n0 + wid * 16 + gid;
    int gn1 = gn0 + 8;
#pragma unroll
    for (int nt = 0; nt < 8; nt++) {
        int c = nt * 8 + tig * 2;
        if (gn0 < NN) {
            float2 hv = *reinterpret_cast<const float2*>(&h_in[gn0 * 64 + c]);
            float2 o;
            o.x = fmaxf(acc[nt][0] + hv.x, 0.f);
            o.y = fmaxf(acc[nt][1] + hv.y, 0.f);
            *reinterpret_cast<float2*>(&h_out[gn0 * 64 + c]) = o;
        }
        if (gn1 < NN) {
            float2 hv = *reinterpret_cast<const float2*>(&h_in[gn1 * 64 + c]);
            float2 o;
            o.x = fmaxf(acc[nt][2] + hv.x, 0.f);
            o.y = fmaxf(acc[nt][3] + hv.y, 0.f);
            *reinterpret_cast<float2*>(&h_out[gn1 * 64 + c]) = o;
        }
    }
}

// ---------------- fc1 ----------------
__global__ void __launch_bounds__(256) fc1_kernel(const float* __restrict__ h_in,
                                                  const float* __restrict__ w,
                                                  const float* __restrict__ b,
                                                  float* __restrict__ out) {
    __shared__ float s_w[64 * 16];
    __shared__ float s_b[16];
    int t = threadIdx.x;
    for (int idx = t; idx < 64 * 16; idx += 256) s_w[idx] = w[idx];
    if (t < 16) s_b[t] = b[t];
    __syncthreads();
    int n = blockIdx.x * 256 + t;
    if (n < NN) {
        float hr[64];
#pragma unroll
        for (int i = 0; i < 16; i++) {
            float4 v = *reinterpret_cast<const float4*>(&h_in[n * 64 + i * 4]);
            hr[4 * i] = v.x; hr[4 * i + 1] = v.y; hr[4 * i + 2] = v.z; hr[4 * i + 3] = v.w;
        }
        float o[16];
#pragma unroll
        for (int c = 0; c < 16; c++) {
            float s = s_b[c];
#pragma unroll
            for (int f = 0; f < 64; f++) s += hr[f] * s_w[f * 16 + c];
            o[c] = s;
        }
#pragma unroll
        for (int i = 0; i < 4; i++) {
            *reinterpret_cast<float4*>(&out[n * 16 + i * 4]) =
                make_float4(o[4 * i], o[4 * i + 1], o[4 * i + 2], o[4 * i + 3]);
        }
    }
}

// ---------------- launch ----------------
extern "C" void kernel_launch(void* const* d_in, const int* in_sizes, int n_in,
                              void* d_out, int out_size) {
    const float* x     = (const float*)d_in[0];
    const int*   ei    = (const int*)  d_in[1];
    const float* fc0w  = (const float*)d_in[2];
    const float* fc0b  = (const float*)d_in[3];
    const float* fc1w  = (const float*)d_in[4];
    const float* fc1b  = (const float*)d_in[5];
    const float* envw  = (const float*)d_in[6];
    const float* envb  = (const float*)d_in[7];
    const float* convw = (const float*)d_in[8];
    float* out = (float*)d_out;

    const int* row = ei;
    const int* col = ei + EE;

    cudaFuncSetAttribute(fc0_mma_kernel, cudaFuncAttributeMaxDynamicSharedMemorySize, FC0_SMEM);
    cudaFuncSetAttribute(conv_mma_kernel, cudaFuncAttributeMaxDynamicSharedMemorySize, CONV_SMEM);

    const int nscan = (NN + 1023) / 1024;   // 98

    // CSR build (edges fixed across layers)
    zero_deg_kernel<<<(NN + 255) / 256, 256>>>();
    deg_kernel<<<(EE + 255) / 256, 256>>>(col);
    dn_kernel<<<(NN + 255) / 256, 256>>>();
    scan_block_kernel<<<nscan, 1024>>>();
    scan_bsum_kernel<<<1, 32>>>(nscan);
    scan_add_kernel<<<nscan, 1024>>>();
    fill_csr_kernel<<<(EE + 255) / 256, 256>>>(row, col);

    // pre-packed bf16 hi/lo B fragments
    wpack_kernel<<<48, 256>>>(convw);
    wpack0_kernel<<<2, 256>>>(fc0w);

    fc0_mma_kernel<<<(NN + 127) / 128, 256, FC0_SMEM>>>(x, fc0b);

    // resolve device-symbol addresses for ping-pong (host-side, not an alloc)
    float* ha = nullptr; float* hb = nullptr;
    cudaGetSymbolAddress((void**)&ha, g_ha);
    cudaGetSymbolAddress((void**)&hb, g_hb);

    const float* hin = ha;
    float* hout = hb;
    for (int i = 0; i < LL; i++) {
        conv_mma_kernel<<<(NN + 127) / 128, 256, CONV_SMEM>>>(
            hin, hout, envw + i * 2 * HH * KK, envb + i * KK, i);
        const float* tmp = hin;
        hin = hout;
        hout = (float*)tmp;
    }

    fc1_kernel<<<(NN + 255) / 256, 256>>>(hin, fc1w, fc1b, out);
}

// round 8
// speedup vs baseline: 1.6910x; 1.6910x over previous
#include <cuda_runtime.h>
#include <cuda_bf16.h>
#include <cstdint>

#define NN 100000
#define DD 128
#define HH 64
#define KK 8
#define LL 3
#define CC 16
#define EE 1600000

// ---------------- device scratch ----------------
__device__ __align__(128) float g_h[NN * HH];
__device__ __align__(128) float g_agg[NN * HH];
__device__ __align__(128) float g_dn[NN];
__device__ __align__(128) int   g_deg[NN];
__device__ __align__(128) int   g_ptr[NN + 1];
__device__ __align__(128) int   g_cur[NN];
__device__ __align__(128) int   g_bsum[128];
__device__ __align__(128) uint2 g_csr[EE];            // (src, val bits)
// pre-packed B fragments: conv [48 images], fc0 [2 images]; head k of layer l
// occupies images (l*8+k)*2 .. +1 -> 4096 contiguous uint2 = 32KB
__device__ __align__(128) uint2 g_wpack[48 * 2048];
__device__ __align__(128) uint2 g_wpack0[2 * 2048];

// single dynamic smem symbol shared by all kernels
extern __shared__ unsigned char dyn_smem[];

__device__ __forceinline__ uint16_t bf16_bits(float v) {
    __nv_bfloat16 b = __float2bfloat16(v);
    return *reinterpret_cast<uint16_t*>(&b);
}
__device__ __forceinline__ float bf16_val(float v) {
    return __bfloat162float(__float2bfloat16(v));
}
__device__ __forceinline__ uint32_t pack2(uint16_t lo, uint16_t hi) {
    return (uint32_t)lo | ((uint32_t)hi << 16);
}

// mma.sync m16n8k16 bf16 (row.col), f32 accumulate
__device__ __forceinline__ void hmma(float* d, const uint32_t* a, uint2 b) {
    asm volatile(
        "mma.sync.aligned.m16n8k16.row.col.f32.bf16.bf16.f32 "
        "{%0,%1,%2,%3}, {%4,%5,%6,%7}, {%8,%9}, {%0,%1,%2,%3};"
        : "+f"(d[0]), "+f"(d[1]), "+f"(d[2]), "+f"(d[3])
        : "r"(a[0]), "r"(a[1]), "r"(a[2]), "r"(a[3]), "r"(b.x), "r"(b.y));
}

__device__ __forceinline__ void cp_async16(void* dst, const void* src) {
    uint32_t d = (uint32_t)__cvta_generic_to_shared(dst);
    asm volatile("cp.async.cg.shared.global [%0], [%1], 16;" :: "r"(d), "l"(src));
}
#define CP_COMMIT() asm volatile("cp.async.commit_group;" ::: "memory")

// ---------------- CSR build kernels ----------------
__global__ void zero_deg_kernel() {
    int i = blockIdx.x * blockDim.x + threadIdx.x;
    if (i < NN) g_deg[i] = 0;
}
__global__ void deg_kernel(const int* __restrict__ col) {
    int e = blockIdx.x * blockDim.x + threadIdx.x;
    if (e < EE) atomicAdd(&g_deg[col[e]], 1);
}
__global__ void dn_kernel() {
    int i = blockIdx.x * blockDim.x + threadIdx.x;
    if (i < NN) {
        int d = g_deg[i];
        g_dn[i] = d > 0 ? rsqrtf((float)d) : 0.f;
    }
}
__global__ void __launch_bounds__(1024) scan_block_kernel() {
    __shared__ int s[1024];
    int t = threadIdx.x;
    int i = blockIdx.x * 1024 + t;
    int v = (i < NN) ? g_deg[i] : 0;
    s[t] = v;
    __syncthreads();
#pragma unroll
    for (int off = 1; off < 1024; off <<= 1) {
        int x = (t >= off) ? s[t - off] : 0;
        __syncthreads();
        s[t] += x;
        __syncthreads();
    }
    if (i < NN) g_ptr[i] = s[t] - v;  // exclusive within block
    if (t == 1023) g_bsum[blockIdx.x] = s[1023];
}
// 128-thread scan over block sums (nblocks <= 128)
__global__ void __launch_bounds__(128) scan_bsum_kernel(int nblocks) {
    __shared__ int s[128];
    int t = threadIdx.x;
    int v = (t < nblocks) ? g_bsum[t] : 0;
    s[t] = v;
    __syncthreads();
#pragma unroll
    for (int off = 1; off < 128; off <<= 1) {
        int x = (t >= off) ? s[t - off] : 0;
        __syncthreads();
        s[t] += x;
        __syncthreads();
    }
    if (t < nblocks) g_bsum[t] = s[t] - v;   // exclusive
    if (t == 127) g_ptr[NN] = s[127];
}
__global__ void __launch_bounds__(1024) scan_add_kernel() {
    int i = blockIdx.x * 1024 + threadIdx.x;
    if (i < NN) {
        int p = g_ptr[i] + g_bsum[blockIdx.x];
        g_ptr[i] = p;
        g_cur[i] = p;
    }
}
__global__ void fill_csr_kernel(const int* __restrict__ row, const int* __restrict__ col) {
    int e = blockIdx.x * blockDim.x + threadIdx.x;
    if (e < EE) {
        int c = col[e], r = row[e];
        int p = atomicAdd(&g_cur[c], 1);
        g_csr[p] = make_uint2((unsigned)r, __float_as_uint(g_dn[r] * g_dn[c]));
    }
}

// ---------------- gather: agg[n] = sum_j val_j * h[src_j]  (warp per node) ----------------
__global__ void __launch_bounds__(256) gather_kernel() {
    int n = blockIdx.x * 8 + (threadIdx.x >> 5);
    if (n >= NN) return;
    int lane = threadIdx.x & 31;
    int js = g_ptr[n], je = g_ptr[n + 1];
    const float2* h2 = reinterpret_cast<const float2*>(g_h);
    float2 acc = make_float2(0.f, 0.f);
    int j = js;
    for (; j + 4 <= je; j += 4) {
        uint2 c0 = g_csr[j], c1 = g_csr[j + 1], c2 = g_csr[j + 2], c3 = g_csr[j + 3];
        float2 a0 = h2[c0.x * 32 + lane];
        float2 a1 = h2[c1.x * 32 + lane];
        float2 a2 = h2[c2.x * 32 + lane];
        float2 a3 = h2[c3.x * 32 + lane];
        float v0 = __uint_as_float(c0.y), v1 = __uint_as_float(c1.y);
        float v2 = __uint_as_float(c2.y), v3 = __uint_as_float(c3.y);
        acc.x += v0 * a0.x; acc.y += v0 * a0.y;
        acc.x += v1 * a1.x; acc.y += v1 * a1.y;
        acc.x += v2 * a2.x; acc.y += v2 * a2.y;
        acc.x += v3 * a3.x; acc.y += v3 * a3.y;
    }
    for (; j < je; j++) {
        uint2 c = g_csr[j];
        float2 a = h2[c.x * 32 + lane];
        float v = __uint_as_float(c.y);
        acc.x += v * a.x; acc.y += v * a.y;
    }
    reinterpret_cast<float2*>(g_agg)[n * 32 + lane] = acc;
}

// ---------------- W prepack: bf16 hi/lo split, HMMA B-fragment order ----------------
__device__ __forceinline__ void wpack_img(const float* __restrict__ w, uint2* __restrict__ dst, int sel) {
    for (int i = threadIdx.x; i < 2048; i += 256) {
        int lane = i & 31;
        int nt = (i >> 5) & 7;
        int ks = i >> 8;
        int tig = lane & 3, gid = lane >> 2;
        int n = nt * 8 + gid;
        int k0 = ks * 16 + tig * 2;
        float v0 = w[(k0 + 0) * 64 + n];
        float v1 = w[(k0 + 1) * 64 + n];
        float v2 = w[(k0 + 8) * 64 + n];
        float v3 = w[(k0 + 9) * 64 + n];
        uint16_t h0, h1, h2, h3;
        if (sel == 0) {
            h0 = bf16_bits(v0); h1 = bf16_bits(v1); h2 = bf16_bits(v2); h3 = bf16_bits(v3);
        } else {
            h0 = bf16_bits(v0 - bf16_val(v0));
            h1 = bf16_bits(v1 - bf16_val(v1));
            h2 = bf16_bits(v2 - bf16_val(v2));
            h3 = bf16_bits(v3 - bf16_val(v3));
        }
        dst[i] = make_uint2(pack2(h0, h1), pack2(h2, h3));
    }
}
__global__ void wpack_kernel(const float* __restrict__ cw) {
    int img = blockIdx.x;          // 0..47
    wpack_img(cw + (img >> 1) * 8192, g_wpack + img * 2048, img & 1);
}
__global__ void wpack0_kernel(const float* __restrict__ w0) {
    wpack_img(w0, g_wpack0 + blockIdx.x * 2048, blockIdx.x);
}

// ---------------- smem layout ----------------
#define A_STRIDE 136
#define SM_A_BYTES (128 * A_STRIDE * 2)          // 34816
#define SM_AH 0
#define SM_AL SM_A_BYTES
#define SM_E  (2 * SM_A_BYTES)                   // 69632 (beyond 64KB B ring)
#define SM_EW (SM_E + 128 * 8 * 4)               // 73728
#define CONV_SMEM (SM_EW + 520 * 4)              // 75808
#define FC0_SMEM  (2 * SM_A_BYTES)

// ---------------- fc0 via HMMA: h = relu(x @ w + b) ----------------
__global__ void __launch_bounds__(256, 1) fc0_mma_kernel(const float* __restrict__ x,
                                                         const float* __restrict__ bias) {
    unsigned char* smb = dyn_smem;
    uint16_t* Ah = reinterpret_cast<uint16_t*>(smb + SM_AH);
    uint16_t* Al = reinterpret_cast<uint16_t*>(smb + SM_AL);

    int t = threadIdx.x;
    int wid = t >> 5, lane = t & 31;
    int tig = lane & 3, gid = lane >> 2;
    int n0 = blockIdx.x * 128;

    const float4* x4 = reinterpret_cast<const float4*>(x);
    for (int idx = t; idx < 4096; idx += 256) {
        int r = idx >> 5, j = idx & 31;
        int gn = n0 + r;
        float4 v = make_float4(0.f, 0.f, 0.f, 0.f);
        if (gn < NN) v = x4[gn * 32 + j];
        uint16_t hx = bf16_bits(v.x), hy = bf16_bits(v.y);
        uint16_t hz = bf16_bits(v.z), hw = bf16_bits(v.w);
        uint16_t lx = bf16_bits(v.x - bf16_val(v.x));
        uint16_t ly = bf16_bits(v.y - bf16_val(v.y));
        uint16_t lz = bf16_bits(v.z - bf16_val(v.z));
        uint16_t lw = bf16_bits(v.w - bf16_val(v.w));
        *reinterpret_cast<uint2*>(&Ah[r * A_STRIDE + j * 4]) = make_uint2(pack2(hx, hy), pack2(hz, hw));
        *reinterpret_cast<uint2*>(&Al[r * A_STRIDE + j * 4]) = make_uint2(pack2(lx, ly), pack2(lz, lw));
    }
    __syncthreads();

    uint32_t ah[8][4], al[8][4];
    int fr0 = wid * 16 + gid;
#pragma unroll
    for (int s = 0; s < 8; s++) {
        int kc = s * 16 + tig * 2;
        ah[s][0] = *reinterpret_cast<const uint32_t*>(&Ah[fr0 * A_STRIDE + kc]);
        ah[s][1] = *reinterpret_cast<const uint32_t*>(&Ah[(fr0 + 8) * A_STRIDE + kc]);
        ah[s][2] = *reinterpret_cast<const uint32_t*>(&Ah[fr0 * A_STRIDE + kc + 8]);
        ah[s][3] = *reinterpret_cast<const uint32_t*>(&Ah[(fr0 + 8) * A_STRIDE + kc + 8]);
        al[s][0] = *reinterpret_cast<const uint32_t*>(&Al[fr0 * A_STRIDE + kc]);
        al[s][1] = *reinterpret_cast<const uint32_t*>(&Al[(fr0 + 8) * A_STRIDE + kc]);
        al[s][2] = *reinterpret_cast<const uint32_t*>(&Al[fr0 * A_STRIDE + kc + 8]);
        al[s][3] = *reinterpret_cast<const uint32_t*>(&Al[(fr0 + 8) * A_STRIDE + kc + 8]);
    }

    float acc[8][4];
#pragma unroll
    for (int nt = 0; nt < 8; nt++)
#pragma unroll
        for (int i = 0; i < 4; i++) acc[nt][i] = 0.f;

    const uint2* bh = g_wpack0;
    const uint2* bl = g_wpack0 + 2048;
#pragma unroll
    for (int s = 0; s < 8; s++) {
        uint2 b[8];
#pragma unroll
        for (int nt = 0; nt < 8; nt++) b[nt] = bh[(s * 8 + nt) * 32 + lane];
#pragma unroll
        for (int nt = 0; nt < 8; nt++) hmma(acc[nt], ah[s], b[nt]);
#pragma unroll
        for (int nt = 0; nt < 8; nt++) hmma(acc[nt], al[s], b[nt]);
    }
#pragma unroll
    for (int s = 0; s < 8; s++) {
        uint2 b[8];
#pragma unroll
        for (int nt = 0; nt < 8; nt++) b[nt] = bl[(s * 8 + nt) * 32 + lane];
#pragma unroll
        for (int nt = 0; nt < 8; nt++) hmma(acc[nt], ah[s], b[nt]);
    }

    int gn0 = n0 + wid * 16 + gid;
    int gn1 = gn0 + 8;
#pragma unroll
    for (int nt = 0; nt < 8; nt++) {
        int c = nt * 8 + tig * 2;
        float2 bi = *reinterpret_cast<const float2*>(&bias[c]);
        if (gn0 < NN) {
            float2 o;
            o.x = fmaxf(acc[nt][0] + bi.x, 0.f);
            o.y = fmaxf(acc[nt][1] + bi.y, 0.f);
            *reinterpret_cast<float2*>(&g_h[gn0 * 64 + c]) = o;
        }
        if (gn1 < NN) {
            float2 o;
            o.x = fmaxf(acc[nt][2] + bi.x, 0.f);
            o.y = fmaxf(acc[nt][3] + bi.y, 0.f);
            *reinterpret_cast<float2*>(&g_h[gn1 * 64 + c]) = o;
        }
    }
}

// ---------------- conv layer: gating + mma.sync bf16x3 with smem-staged B ----------------
__global__ void __launch_bounds__(256, 1) conv_mma_kernel(const float* __restrict__ ew,
                                                          const float* __restrict__ eb,
                                                          int layer) {
    unsigned char* smb = dyn_smem;
    uint16_t* Ah = reinterpret_cast<uint16_t*>(smb + SM_AH);
    uint16_t* Al = reinterpret_cast<uint16_t*>(smb + SM_AL);
    float* s_e = reinterpret_cast<float*>(smb + SM_E);
    float* s_ew = reinterpret_cast<float*>(smb + SM_EW);

    int t = threadIdx.x;
    int wid = t >> 5, lane = t & 31;
    int tig = lane & 3, gid = lane >> 2;
    int n0 = blockIdx.x * 128;

    for (int i = t; i < 520; i += 256) s_ew[i] = (i < 512) ? ew[i] : eb[i - 512];

    // ---- build A tile (agg || h, bf16 hi/lo split) ----
    const float4* agg4 = reinterpret_cast<const float4*>(g_agg);
    const float4* h4 = reinterpret_cast<const float4*>(g_h);
    for (int idx = t; idx < 4096; idx += 256) {
        int r = idx >> 5, j = idx & 31;
        int gn = n0 + r;
        float4 v = make_float4(0.f, 0.f, 0.f, 0.f);
        if (gn < NN) v = (j < 16) ? agg4[gn * 16 + j] : h4[gn * 16 + (j - 16)];
        uint16_t hx = bf16_bits(v.x), hy = bf16_bits(v.y);
        uint16_t hz = bf16_bits(v.z), hw = bf16_bits(v.w);
        uint16_t lx = bf16_bits(v.x - bf16_val(v.x));
        uint16_t ly = bf16_bits(v.y - bf16_val(v.y));
        uint16_t lz = bf16_bits(v.z - bf16_val(v.z));
        uint16_t lw = bf16_bits(v.w - bf16_val(v.w));
        *reinterpret_cast<uint2*>(&Ah[r * A_STRIDE + j * 4]) = make_uint2(pack2(hx, hy), pack2(hz, hw));
        *reinterpret_cast<uint2*>(&Al[r * A_STRIDE + j * 4]) = make_uint2(pack2(lx, ly), pack2(lz, lw));
    }
    __syncthreads();

    // ---- A fragments into registers ----
    uint32_t ah[8][4], al[8][4];
    int fr0 = wid * 16 + gid;
#pragma unroll
    for (int s = 0; s < 8; s++) {
        int kc = s * 16 + tig * 2;
        ah[s][0] = *reinterpret_cast<const uint32_t*>(&Ah[fr0 * A_STRIDE + kc]);
        ah[s][1] = *reinterpret_cast<const uint32_t*>(&Ah[(fr0 + 8) * A_STRIDE + kc]);
        ah[s][2] = *reinterpret_cast<const uint32_t*>(&Ah[fr0 * A_STRIDE + kc + 8]);
        ah[s][3] = *reinterpret_cast<const uint32_t*>(&Ah[(fr0 + 8) * A_STRIDE + kc + 8]);
        al[s][0] = *reinterpret_cast<const uint32_t*>(&Al[fr0 * A_STRIDE + kc]);
        al[s][1] = *reinterpret_cast<const uint32_t*>(&Al[(fr0 + 8) * A_STRIDE + kc]);
        al[s][2] = *reinterpret_cast<const uint32_t*>(&Al[fr0 * A_STRIDE + kc + 8]);
        al[s][3] = *reinterpret_cast<const uint32_t*>(&Al[(fr0 + 8) * A_STRIDE + kc + 8]);
    }
    __syncthreads();   // done reading A smem; B ring may overwrite it

    const uint2* wp = g_wpack + layer * 8 * 4096;   // 4096 uint2 (32KB) per head

    // prefetch heads 0,1 into slots 0,1
    {
        uint2* dst0 = reinterpret_cast<uint2*>(smb);
        const uint2* s0 = wp;
        for (int i = 0; i < 8; i++) cp_async16(dst0 + (i * 256 + t) * 2, s0 + (i * 256 + t) * 2);
        CP_COMMIT();
        uint2* dst1 = reinterpret_cast<uint2*>(smb + 32768);
        const uint2* s1 = wp + 4096;
        for (int i = 0; i < 8; i++) cp_async16(dst1 + (i * 256 + t) * 2, s1 + (i * 256 + t) * 2);
        CP_COMMIT();
    }

    // ---- gating (threads 0..127, one node each), overlapped with prefetch ----
    if (t < 128) {
        int gn = n0 + t;
        float hrow[64];
        if (gn < NN) {
#pragma unroll
            for (int i = 0; i < 16; i++) {
                float4 v = h4[gn * 16 + i];
                hrow[4 * i] = v.x; hrow[4 * i + 1] = v.y;
                hrow[4 * i + 2] = v.z; hrow[4 * i + 3] = v.w;
            }
        } else {
#pragma unroll
            for (int i = 0; i < 64; i++) hrow[i] = 0.f;
        }
        float lg[8];
#pragma unroll
        for (int k = 0; k < 8; k++) lg[k] = s_ew[512 + k];
#pragma unroll 8
        for (int f = 0; f < 64; f++) {
            float hv = hrow[f];
            float4 w0 = *reinterpret_cast<const float4*>(&s_ew[f * 8]);
            float4 w1 = *reinterpret_cast<const float4*>(&s_ew[f * 8 + 4]);
            lg[0] += hv * w0.x; lg[1] += hv * w0.y; lg[2] += hv * w0.z; lg[3] += hv * w0.w;
            lg[4] += hv * w1.x; lg[5] += hv * w1.y; lg[6] += hv * w1.z; lg[7] += hv * w1.w;
        }
        float m = -1e30f;
#pragma unroll
        for (int k = 0; k < 8; k++) m = fmaxf(m, lg[k]);
        float sum = 0.f;
#pragma unroll
        for (int k = 0; k < 8; k++) { lg[k] = expf(lg[k] - m); sum += lg[k]; }
        float inv = 1.f / sum;
#pragma unroll
        for (int k = 0; k < 8; k++) {
            float pi = lg[k] * inv;
            s_e[t * 8 + k] = (pi > 0.1f) ? pi : 0.f;
        }
    }

    // ---- main MMA loop over 8 heads, B double-buffered in smem ----
    float acc[8][4];
#pragma unroll
    for (int nt = 0; nt < 8; nt++)
#pragma unroll
        for (int i = 0; i < 4; i++) acc[nt][i] = 0.f;

#pragma unroll 1
    for (int k = 0; k < 8; k++) {
        if (k < 7) asm volatile("cp.async.wait_group 1;" ::: "memory");
        else       asm volatile("cp.async.wait_group 0;" ::: "memory");
        __syncthreads();   // B slot k&1 visible CTA-wide; also publishes s_e on k=0

        int slot = k & 1;
        const uint2* bh = reinterpret_cast<const uint2*>(smb + slot * 32768);
        const uint2* bl = bh + 2048;

        float acck[8][4];
#pragma unroll
        for (int nt = 0; nt < 8; nt++)
#pragma unroll
            for (int i = 0; i < 4; i++) acck[nt][i] = 0.f;

        // pass 1: (Ah + Al) x Bh
#pragma unroll
        for (int s = 0; s < 8; s++) {
            uint2 b[8];
#pragma unroll
            for (int nt = 0; nt < 8; nt++) b[nt] = bh[(s * 8 + nt) * 32 + lane];
#pragma unroll
            for (int nt = 0; nt < 8; nt++) hmma(acck[nt], ah[s], b[nt]);
#pragma unroll
            for (int nt = 0; nt < 8; nt++) hmma(acck[nt], al[s], b[nt]);
        }
        // pass 2: Ah x Bl
#pragma unroll
        for (int s = 0; s < 8; s++) {
            uint2 b[8];
#pragma unroll
            for (int nt = 0; nt < 8; nt++) b[nt] = bl[(s * 8 + nt) * 32 + lane];
#pragma unroll
            for (int nt = 0; nt < 8; nt++) hmma(acck[nt], ah[s], b[nt]);
        }

        float e0 = s_e[(wid * 16 + gid) * 8 + k];
        float e1 = s_e[(wid * 16 + gid + 8) * 8 + k];
#pragma unroll
        for (int nt = 0; nt < 8; nt++) {
            acc[nt][0] += e0 * acck[nt][0];
            acc[nt][1] += e0 * acck[nt][1];
            acc[nt][2] += e1 * acck[nt][2];
            acc[nt][3] += e1 * acck[nt][3];
        }

        if (k + 2 < 8) {
            __syncthreads();   // all warps done with slot before overwrite
            uint2* dst = reinterpret_cast<uint2*>(smb + slot * 32768);
            const uint2* src = wp + (k + 2) * 4096;
            for (int i = 0; i < 8; i++) cp_async16(dst + (i * 256 + t) * 2, src + (i * 256 + t) * 2);
            CP_COMMIT();
        }
    }

    // ---- epilogue: h = relu(acc + h), in-place (CTA owns its rows; gather done in prior kernel) ----
    int gn0 = n0 + wid * 16 + gid;
    int gn1 = gn0 + 8;
#pragma unroll
    for (int nt = 0; nt < 8; nt++) {
        int c = nt * 8 + tig * 2;
        if (gn0 < NN) {
            float2 hv = *reinterpret_cast<const float2*>(&g_h[gn0 * 64 + c]);
            float2 o;
            o.x = fmaxf(acc[nt][0] + hv.x, 0.f);
            o.y = fmaxf(acc[nt][1] + hv.y, 0.f);
            *reinterpret_cast<float2*>(&g_h[gn0 * 64 + c]) = o;
        }
        if (gn1 < NN) {
            float2 hv = *reinterpret_cast<const float2*>(&g_h[gn1 * 64 + c]);
            float2 o;
            o.x = fmaxf(acc[nt][2] + hv.x, 0.f);
            o.y = fmaxf(acc[nt][3] + hv.y, 0.f);
            *reinterpret_cast<float2*>(&g_h[gn1 * 64 + c]) = o;
        }
    }
}

// ---------------- fc1 ----------------
__global__ void __launch_bounds__(256) fc1_kernel(const float* __restrict__ w,
                                                  const float* __restrict__ b,
                                                  float* __restrict__ out) {
    __shared__ float s_w[64 * 16];
    __shared__ float s_b[16];
    int t = threadIdx.x;
    for (int idx = t; idx < 64 * 16; idx += 256) s_w[idx] = w[idx];
    if (t < 16) s_b[t] = b[t];
    __syncthreads();
    int n = blockIdx.x * 256 + t;
    if (n < NN) {
        float hr[64];
#pragma unroll
        for (int i = 0; i < 16; i++) {
            float4 v = *reinterpret_cast<const float4*>(&g_h[n * 64 + i * 4]);
            hr[4 * i] = v.x; hr[4 * i + 1] = v.y; hr[4 * i + 2] = v.z; hr[4 * i + 3] = v.w;
        }
        float o[16];
#pragma unroll
        for (int c = 0; c < 16; c++) {
            float s = s_b[c];
#pragma unroll
            for (int f = 0; f < 64; f++) s += hr[f] * s_w[f * 16 + c];
            o[c] = s;
        }
#pragma unroll
        for (int i = 0; i < 4; i++) {
            *reinterpret_cast<float4*>(&out[n * 16 + i * 4]) =
                make_float4(o[4 * i], o[4 * i + 1], o[4 * i + 2], o[4 * i + 3]);
        }
    }
}

// ---------------- launch ----------------
extern "C" void kernel_launch(void* const* d_in, const int* in_sizes, int n_in,
                              void* d_out, int out_size) {
    const float* x     = (const float*)d_in[0];
    const int*   ei    = (const int*)  d_in[1];
    const float* fc0w  = (const float*)d_in[2];
    const float* fc0b  = (const float*)d_in[3];
    const float* fc1w  = (const float*)d_in[4];
    const float* fc1b  = (const float*)d_in[5];
    const float* envw  = (const float*)d_in[6];
    const float* envb  = (const float*)d_in[7];
    const float* convw = (const float*)d_in[8];
    float* out = (float*)d_out;

    const int* row = ei;
    const int* col = ei + EE;

    cudaFuncSetAttribute(fc0_mma_kernel, cudaFuncAttributeMaxDynamicSharedMemorySize, FC0_SMEM);
    cudaFuncSetAttribute(conv_mma_kernel, cudaFuncAttributeMaxDynamicSharedMemorySize, CONV_SMEM);

    const int nscan = (NN + 1023) / 1024;   // 98

    // CSR build (edges fixed across layers)
    zero_deg_kernel<<<(NN + 255) / 256, 256>>>();
    deg_kernel<<<(EE + 255) / 256, 256>>>(col);
    dn_kernel<<<(NN + 255) / 256, 256>>>();
    scan_block_kernel<<<nscan, 1024>>>();
    scan_bsum_kernel<<<1, 128>>>(nscan);
    scan_add_kernel<<<nscan, 1024>>>();
    fill_csr_kernel<<<(EE + 255) / 256, 256>>>(row, col);

    // pre-packed bf16 hi/lo B fragments
    wpack_kernel<<<48, 256>>>(convw);
    wpack0_kernel<<<2, 256>>>(fc0w);

    fc0_mma_kernel<<<(NN + 127) / 128, 256, FC0_SMEM>>>(x, fc0b);

    for (int i = 0; i < LL; i++) {
        gather_kernel<<<(NN + 7) / 8, 256>>>();
        conv_mma_kernel<<<(NN + 127) / 128, 256, CONV_SMEM>>>(
            envw + i * 2 * HH * KK, envb + i * KK, i);
    }

    fc1_kernel<<<(NN + 255) / 256, 256>>>(fc1w, fc1b, out);
}

// round 9
// speedup vs baseline: 1.7331x; 1.0249x over previous
#include <cuda_runtime.h>
#include <cuda_bf16.h>
#include <cstdint>

#define NN 100000
#define DD 128
#define HH 64
#define KK 8
#define LL 3
#define CC 16
#define EE 1600000

// ---------------- device scratch ----------------
__device__ __align__(128) float g_h[NN * HH];
__device__ __align__(128) float g_agg[NN * HH];
__device__ __align__(128) float g_dn[NN];
__device__ __align__(128) int   g_deg[NN];
__device__ __align__(128) int   g_ptr[NN + 1];
__device__ __align__(128) int   g_cur[NN];
__device__ __align__(128) int   g_bsum[128];
__device__ __align__(128) uint2 g_csr[EE];            // (src, val bits)
// pre-packed B fragments: conv [48 images], fc0 [2 images]; head k of layer l
// occupies images (l*8+k)*2 .. +1 -> 4096 contiguous uint2 = 32KB
__device__ __align__(128) uint2 g_wpack[48 * 2048];
__device__ __align__(128) uint2 g_wpack0[2 * 2048];

// single dynamic smem symbol shared by all kernels
extern __shared__ unsigned char dyn_smem[];

__device__ __forceinline__ uint16_t bf16_bits(float v) {
    __nv_bfloat16 b = __float2bfloat16(v);
    return *reinterpret_cast<uint16_t*>(&b);
}
__device__ __forceinline__ float bf16_val(float v) {
    return __bfloat162float(__float2bfloat16(v));
}
__device__ __forceinline__ uint32_t pack2(uint16_t lo, uint16_t hi) {
    return (uint32_t)lo | ((uint32_t)hi << 16);
}

// mma.sync m16n8k16 bf16 (row.col), f32 accumulate
__device__ __forceinline__ void hmma(float* d, const uint32_t* a, uint2 b) {
    asm volatile(
        "mma.sync.aligned.m16n8k16.row.col.f32.bf16.bf16.f32 "
        "{%0,%1,%2,%3}, {%4,%5,%6,%7}, {%8,%9}, {%0,%1,%2,%3};"
        : "+f"(d[0]), "+f"(d[1]), "+f"(d[2]), "+f"(d[3])
        : "r"(a[0]), "r"(a[1]), "r"(a[2]), "r"(a[3]), "r"(b.x), "r"(b.y));
}

__device__ __forceinline__ void cp_async16(void* dst, const void* src) {
    uint32_t d = (uint32_t)__cvta_generic_to_shared(dst);
    asm volatile("cp.async.cg.shared.global [%0], [%1], 16;" :: "r"(d), "l"(src));
}
#define CP_COMMIT() asm volatile("cp.async.commit_group;" ::: "memory")

// ---------------- CSR build kernels ----------------
__global__ void zero_deg_kernel() {
    int i = blockIdx.x * blockDim.x + threadIdx.x;
    if (i < NN) g_deg[i] = 0;
}
__global__ void deg_kernel(const int* __restrict__ col) {
    int e = blockIdx.x * blockDim.x + threadIdx.x;
    if (e < EE) atomicAdd(&g_deg[col[e]], 1);
}
__global__ void dn_kernel() {
    int i = blockIdx.x * blockDim.x + threadIdx.x;
    if (i < NN) {
        int d = g_deg[i];
        g_dn[i] = d > 0 ? rsqrtf((float)d) : 0.f;
    }
}
__global__ void __launch_bounds__(1024) scan_block_kernel() {
    __shared__ int s[1024];
    int t = threadIdx.x;
    int i = blockIdx.x * 1024 + t;
    int v = (i < NN) ? g_deg[i] : 0;
    s[t] = v;
    __syncthreads();
#pragma unroll
    for (int off = 1; off < 1024; off <<= 1) {
        int x = (t >= off) ? s[t - off] : 0;
        __syncthreads();
        s[t] += x;
        __syncthreads();
    }
    if (i < NN) g_ptr[i] = s[t] - v;  // exclusive within block
    if (t == 1023) g_bsum[blockIdx.x] = s[1023];
}
__global__ void __launch_bounds__(128) scan_bsum_kernel(int nblocks) {
    __shared__ int s[128];
    int t = threadIdx.x;
    int v = (t < nblocks) ? g_bsum[t] : 0;
    s[t] = v;
    __syncthreads();
#pragma unroll
    for (int off = 1; off < 128; off <<= 1) {
        int x = (t >= off) ? s[t - off] : 0;
        __syncthreads();
        s[t] += x;
        __syncthreads();
    }
    if (t < nblocks) g_bsum[t] = s[t] - v;   // exclusive
    if (t == 127) g_ptr[NN] = s[127];
}
__global__ void __launch_bounds__(1024) scan_add_kernel() {
    int i = blockIdx.x * 1024 + threadIdx.x;
    if (i < NN) {
        int p = g_ptr[i] + g_bsum[blockIdx.x];
        g_ptr[i] = p;
        g_cur[i] = p;
    }
}
__global__ void fill_csr_kernel(const int* __restrict__ row, const int* __restrict__ col) {
    int e = blockIdx.x * blockDim.x + threadIdx.x;
    if (e < EE) {
        int c = col[e], r = row[e];
        int p = atomicAdd(&g_cur[c], 1);
        g_csr[p] = make_uint2((unsigned)r, __float_as_uint(g_dn[r] * g_dn[c]));
    }
}

// ---------------- gather: agg[n] = sum_j val_j * h[src_j]  (2 nodes/warp, float4 lanes) ----------------
__global__ void __launch_bounds__(256) gather_kernel() {
    int n = blockIdx.x * 16 + (threadIdx.x >> 4);
    if (n >= NN) return;
    int lane = threadIdx.x & 15;
    int js = g_ptr[n], je = g_ptr[n + 1];
    const float4* h4 = reinterpret_cast<const float4*>(g_h);
    float4 acc = make_float4(0.f, 0.f, 0.f, 0.f);
    int j = js;
    for (; j + 4 <= je; j += 4) {
        uint2 c0 = g_csr[j], c1 = g_csr[j + 1], c2 = g_csr[j + 2], c3 = g_csr[j + 3];
        float4 a0 = h4[c0.x * 16 + lane];
        float4 a1 = h4[c1.x * 16 + lane];
        float4 a2 = h4[c2.x * 16 + lane];
        float4 a3 = h4[c3.x * 16 + lane];
        float v0 = __uint_as_float(c0.y), v1 = __uint_as_float(c1.y);
        float v2 = __uint_as_float(c2.y), v3 = __uint_as_float(c3.y);
        acc.x += v0 * a0.x; acc.y += v0 * a0.y; acc.z += v0 * a0.z; acc.w += v0 * a0.w;
        acc.x += v1 * a1.x; acc.y += v1 * a1.y; acc.z += v1 * a1.z; acc.w += v1 * a1.w;
        acc.x += v2 * a2.x; acc.y += v2 * a2.y; acc.z += v2 * a2.z; acc.w += v2 * a2.w;
        acc.x += v3 * a3.x; acc.y += v3 * a3.y; acc.z += v3 * a3.z; acc.w += v3 * a3.w;
    }
    for (; j < je; j++) {
        uint2 c = g_csr[j];
        float4 a = h4[c.x * 16 + lane];
        float v = __uint_as_float(c.y);
        acc.x += v * a.x; acc.y += v * a.y; acc.z += v * a.z; acc.w += v * a.w;
    }
    reinterpret_cast<float4*>(g_agg)[n * 16 + lane] = acc;
}

// ---------------- W prepack: bf16 hi/lo split, HMMA B-fragment order ----------------
__device__ __forceinline__ void wpack_img(const float* __restrict__ w, uint2* __restrict__ dst, int sel) {
    for (int i = threadIdx.x; i < 2048; i += 256) {
        int lane = i & 31;
        int nt = (i >> 5) & 7;
        int ks = i >> 8;
        int tig = lane & 3, gid = lane >> 2;
        int n = nt * 8 + gid;
        int k0 = ks * 16 + tig * 2;
        float v0 = w[(k0 + 0) * 64 + n];
        float v1 = w[(k0 + 1) * 64 + n];
        float v2 = w[(k0 + 8) * 64 + n];
        float v3 = w[(k0 + 9) * 64 + n];
        uint16_t h0, h1, h2, h3;
        if (sel == 0) {
            h0 = bf16_bits(v0); h1 = bf16_bits(v1); h2 = bf16_bits(v2); h3 = bf16_bits(v3);
        } else {
            h0 = bf16_bits(v0 - bf16_val(v0));
            h1 = bf16_bits(v1 - bf16_val(v1));
            h2 = bf16_bits(v2 - bf16_val(v2));
            h3 = bf16_bits(v3 - bf16_val(v3));
        }
        dst[i] = make_uint2(pack2(h0, h1), pack2(h2, h3));
    }
}
__global__ void wpack_kernel(const float* __restrict__ cw) {
    int img = blockIdx.x;          // 0..47
    wpack_img(cw + (img >> 1) * 8192, g_wpack + img * 2048, img & 1);
}
__global__ void wpack0_kernel(const float* __restrict__ w0) {
    wpack_img(w0, g_wpack0 + blockIdx.x * 2048, blockIdx.x);
}

// ---------------- smem layout ----------------
#define A_STRIDE 136
#define SM_A_BYTES (128 * A_STRIDE * 2)          // 34816
#define SM_AH 0
#define SM_AL SM_A_BYTES
#define SM_E  (2 * SM_A_BYTES)                   // 69632 (beyond 64KB B ring)
#define SM_EW (SM_E + 128 * 8 * 4)               // 73728
#define CONV_SMEM (SM_EW + 520 * 4)              // 75808
#define FC0_SMEM  (2 * SM_A_BYTES)

// ---------------- fc0 via HMMA: h = relu(x @ w + b) ----------------
__global__ void __launch_bounds__(256, 1) fc0_mma_kernel(const float* __restrict__ x,
                                                         const float* __restrict__ bias) {
    unsigned char* smb = dyn_smem;
    uint16_t* Ah = reinterpret_cast<uint16_t*>(smb + SM_AH);
    uint16_t* Al = reinterpret_cast<uint16_t*>(smb + SM_AL);

    int t = threadIdx.x;
    int wid = t >> 5, lane = t & 31;
    int tig = lane & 3, gid = lane >> 2;
    int n0 = blockIdx.x * 128;

    const float4* x4 = reinterpret_cast<const float4*>(x);
    for (int idx = t; idx < 4096; idx += 256) {
        int r = idx >> 5, j = idx & 31;
        int gn = n0 + r;
        float4 v = make_float4(0.f, 0.f, 0.f, 0.f);
        if (gn < NN) v = x4[gn * 32 + j];
        uint16_t hx = bf16_bits(v.x), hy = bf16_bits(v.y);
        uint16_t hz = bf16_bits(v.z), hw = bf16_bits(v.w);
        uint16_t lx = bf16_bits(v.x - bf16_val(v.x));
        uint16_t ly = bf16_bits(v.y - bf16_val(v.y));
        uint16_t lz = bf16_bits(v.z - bf16_val(v.z));
        uint16_t lw = bf16_bits(v.w - bf16_val(v.w));
        *reinterpret_cast<uint2*>(&Ah[r * A_STRIDE + j * 4]) = make_uint2(pack2(hx, hy), pack2(hz, hw));
        *reinterpret_cast<uint2*>(&Al[r * A_STRIDE + j * 4]) = make_uint2(pack2(lx, ly), pack2(lz, lw));
    }
    __syncthreads();

    uint32_t ah[8][4], al[8][4];
    int fr0 = wid * 16 + gid;
#pragma unroll
    for (int s = 0; s < 8; s++) {
        int kc = s * 16 + tig * 2;
        ah[s][0] = *reinterpret_cast<const uint32_t*>(&Ah[fr0 * A_STRIDE + kc]);
        ah[s][1] = *reinterpret_cast<const uint32_t*>(&Ah[(fr0 + 8) * A_STRIDE + kc]);
        ah[s][2] = *reinterpret_cast<const uint32_t*>(&Ah[fr0 * A_STRIDE + kc + 8]);
        ah[s][3] = *reinterpret_cast<const uint32_t*>(&Ah[(fr0 + 8) * A_STRIDE + kc + 8]);
        al[s][0] = *reinterpret_cast<const uint32_t*>(&Al[fr0 * A_STRIDE + kc]);
        al[s][1] = *reinterpret_cast<const uint32_t*>(&Al[(fr0 + 8) * A_STRIDE + kc]);
        al[s][2] = *reinterpret_cast<const uint32_t*>(&Al[fr0 * A_STRIDE + kc + 8]);
        al[s][3] = *reinterpret_cast<const uint32_t*>(&Al[(fr0 + 8) * A_STRIDE + kc + 8]);
    }

    float acc[8][4];
#pragma unroll
    for (int nt = 0; nt < 8; nt++)
#pragma unroll
        for (int i = 0; i < 4; i++) acc[nt][i] = 0.f;

    const uint2* bh = g_wpack0;
    const uint2* bl = g_wpack0 + 2048;
#pragma unroll
    for (int s = 0; s < 8; s++) {
        uint2 b[8];
#pragma unroll
        for (int nt = 0; nt < 8; nt++) b[nt] = bh[(s * 8 + nt) * 32 + lane];
#pragma unroll
        for (int nt = 0; nt < 8; nt++) hmma(acc[nt], ah[s], b[nt]);
#pragma unroll
        for (int nt = 0; nt < 8; nt++) hmma(acc[nt], al[s], b[nt]);
    }
#pragma unroll
    for (int s = 0; s < 8; s++) {
        uint2 b[8];
#pragma unroll
        for (int nt = 0; nt < 8; nt++) b[nt] = bl[(s * 8 + nt) * 32 + lane];
#pragma unroll
        for (int nt = 0; nt < 8; nt++) hmma(acc[nt], ah[s], b[nt]);
    }

    int gn0 = n0 + wid * 16 + gid;
    int gn1 = gn0 + 8;
#pragma unroll
    for (int nt = 0; nt < 8; nt++) {
        int c = nt * 8 + tig * 2;
        float2 bi = *reinterpret_cast<const float2*>(&bias[c]);
        if (gn0 < NN) {
            float2 o;
            o.x = fmaxf(acc[nt][0] + bi.x, 0.f);
            o.y = fmaxf(acc[nt][1] + bi.y, 0.f);
            *reinterpret_cast<float2*>(&g_h[gn0 * 64 + c]) = o;
        }
        if (gn1 < NN) {
            float2 o;
            o.x = fmaxf(acc[nt][2] + bi.x, 0.f);
            o.y = fmaxf(acc[nt][3] + bi.y, 0.f);
            *reinterpret_cast<float2*>(&g_h[gn1 * 64 + c]) = o;
        }
    }
}

// ---------------- conv layer: K-split warps, gating + mma.sync bf16x3, smem-staged B ----------------
// 8 warps = 4 M-groups (32 rows each) x 2 K-groups (K=64 halves).
// Each warp reads only its K-half of B from smem -> LDS B traffic halved.
__global__ void __launch_bounds__(256, 1) conv_mma_kernel(const float* __restrict__ ew,
                                                          const float* __restrict__ eb,
                                                          int layer) {
    unsigned char* smb = dyn_smem;
    uint16_t* Ah = reinterpret_cast<uint16_t*>(smb + SM_AH);
    uint16_t* Al = reinterpret_cast<uint16_t*>(smb + SM_AL);
    float* s_e = reinterpret_cast<float*>(smb + SM_E);
    float* s_ew = reinterpret_cast<float*>(smb + SM_EW);

    int t = threadIdx.x;
    int wid = t >> 5, lane = t & 31;
    int tig = lane & 3, gid = lane >> 2;
    int wk = wid & 1;      // K half
    int wm = wid >> 1;     // M group (32 rows)
    int n0 = blockIdx.x * 128;

    for (int i = t; i < 520; i += 256) s_ew[i] = (i < 512) ? ew[i] : eb[i - 512];

    // ---- build A tile (agg || h, bf16 hi/lo split) ----
    const float4* agg4 = reinterpret_cast<const float4*>(g_agg);
    const float4* h4 = reinterpret_cast<const float4*>(g_h);
    for (int idx = t; idx < 4096; idx += 256) {
        int r = idx >> 5, j = idx & 31;
        int gn = n0 + r;
        float4 v = make_float4(0.f, 0.f, 0.f, 0.f);
        if (gn < NN) v = (j < 16) ? agg4[gn * 16 + j] : h4[gn * 16 + (j - 16)];
        uint16_t hx = bf16_bits(v.x), hy = bf16_bits(v.y);
        uint16_t hz = bf16_bits(v.z), hw = bf16_bits(v.w);
        uint16_t lx = bf16_bits(v.x - bf16_val(v.x));
        uint16_t ly = bf16_bits(v.y - bf16_val(v.y));
        uint16_t lz = bf16_bits(v.z - bf16_val(v.z));
        uint16_t lw = bf16_bits(v.w - bf16_val(v.w));
        *reinterpret_cast<uint2*>(&Ah[r * A_STRIDE + j * 4]) = make_uint2(pack2(hx, hy), pack2(hz, hw));
        *reinterpret_cast<uint2*>(&Al[r * A_STRIDE + j * 4]) = make_uint2(pack2(lx, ly), pack2(lz, lw));
    }
    __syncthreads();

    // ---- A fragments: 2 m-frags x 4 k-steps (own K half) ----
    uint32_t ah[2][4][4], al[2][4][4];
    int fr0 = wm * 32 + gid;
#pragma unroll
    for (int m = 0; m < 2; m++) {
        int base = fr0 + m * 16;
#pragma unroll
        for (int s = 0; s < 4; s++) {
            int kc = (wk * 4 + s) * 16 + tig * 2;
            ah[m][s][0] = *reinterpret_cast<const uint32_t*>(&Ah[base * A_STRIDE + kc]);
            ah[m][s][1] = *reinterpret_cast<const uint32_t*>(&Ah[(base + 8) * A_STRIDE + kc]);
            ah[m][s][2] = *reinterpret_cast<const uint32_t*>(&Ah[base * A_STRIDE + kc + 8]);
            ah[m][s][3] = *reinterpret_cast<const uint32_t*>(&Ah[(base + 8) * A_STRIDE + kc + 8]);
            al[m][s][0] = *reinterpret_cast<const uint32_t*>(&Al[base * A_STRIDE + kc]);
            al[m][s][1] = *reinterpret_cast<const uint32_t*>(&Al[(base + 8) * A_STRIDE + kc]);
            al[m][s][2] = *reinterpret_cast<const uint32_t*>(&Al[base * A_STRIDE + kc + 8]);
            al[m][s][3] = *reinterpret_cast<const uint32_t*>(&Al[(base + 8) * A_STRIDE + kc + 8]);
        }
    }
    __syncthreads();   // done reading A smem; B ring may overwrite it

    const uint2* wp = g_wpack + layer * 8 * 4096;   // 4096 uint2 (32KB) per head

    // prefetch heads 0,1 into slots 0,1
    {
        uint2* dst0 = reinterpret_cast<uint2*>(smb);
        const uint2* s0 = wp;
        for (int i = 0; i < 8; i++) cp_async16(dst0 + (i * 256 + t) * 2, s0 + (i * 256 + t) * 2);
        CP_COMMIT();
        uint2* dst1 = reinterpret_cast<uint2*>(smb + 32768);
        const uint2* s1 = wp + 4096;
        for (int i = 0; i < 8; i++) cp_async16(dst1 + (i * 256 + t) * 2, s1 + (i * 256 + t) * 2);
        CP_COMMIT();
    }

    // ---- gating (threads 0..127, one node each), overlapped with prefetch ----
    if (t < 128) {
        int gn = n0 + t;
        float hrow[64];
        if (gn < NN) {
#pragma unroll
            for (int i = 0; i < 16; i++) {
                float4 v = h4[gn * 16 + i];
                hrow[4 * i] = v.x; hrow[4 * i + 1] = v.y;
                hrow[4 * i + 2] = v.z; hrow[4 * i + 3] = v.w;
            }
        } else {
#pragma unroll
            for (int i = 0; i < 64; i++) hrow[i] = 0.f;
        }
        float lg[8];
#pragma unroll
        for (int k = 0; k < 8; k++) lg[k] = s_ew[512 + k];
#pragma unroll 8
        for (int f = 0; f < 64; f++) {
            float hv = hrow[f];
            float4 w0 = *reinterpret_cast<const float4*>(&s_ew[f * 8]);
            float4 w1 = *reinterpret_cast<const float4*>(&s_ew[f * 8 + 4]);
            lg[0] += hv * w0.x; lg[1] += hv * w0.y; lg[2] += hv * w0.z; lg[3] += hv * w0.w;
            lg[4] += hv * w1.x; lg[5] += hv * w1.y; lg[6] += hv * w1.z; lg[7] += hv * w1.w;
        }
        float m = -1e30f;
#pragma unroll
        for (int k = 0; k < 8; k++) m = fmaxf(m, lg[k]);
        float sum = 0.f;
#pragma unroll
        for (int k = 0; k < 8; k++) { lg[k] = expf(lg[k] - m); sum += lg[k]; }
        float inv = 1.f / sum;
#pragma unroll
        for (int k = 0; k < 8; k++) {
            float pi = lg[k] * inv;
            s_e[t * 8 + k] = (pi > 0.1f) ? pi : 0.f;
        }
    }

    // ---- main MMA loop over 8 heads (nt-outer, partial K per warp) ----
    float acc[2][8][4];
#pragma unroll
    for (int m = 0; m < 2; m++)
#pragma unroll
        for (int nt = 0; nt < 8; nt++)
#pragma unroll
            for (int i = 0; i < 4; i++) acc[m][nt][i] = 0.f;

#pragma unroll 1
    for (int k = 0; k < 8; k++) {
        if (k < 7) asm volatile("cp.async.wait_group 1;" ::: "memory");
        else       asm volatile("cp.async.wait_group 0;" ::: "memory");
        __syncthreads();   // B slot k&1 visible CTA-wide; also publishes s_e on k=0

        int slot = k & 1;
        const uint2* bh = reinterpret_cast<const uint2*>(smb + slot * 32768);
        const uint2* bl = bh + 2048;

        float e00 = s_e[(fr0) * 8 + k];
        float e01 = s_e[(fr0 + 8) * 8 + k];
        float e10 = s_e[(fr0 + 16) * 8 + k];
        float e11 = s_e[(fr0 + 24) * 8 + k];

#pragma unroll
        for (int nt = 0; nt < 8; nt++) {
            float acck[2][4] = {};
            // pass 1: (Ah + Al) x Bh   (own K half)
#pragma unroll
            for (int s = 0; s < 4; s++) {
                uint2 b = bh[((wk * 4 + s) * 8 + nt) * 32 + lane];
                hmma(acck[0], ah[0][s], b);
                hmma(acck[0], al[0][s], b);
                hmma(acck[1], ah[1][s], b);
                hmma(acck[1], al[1][s], b);
            }
            // pass 2: Ah x Bl
#pragma unroll
            for (int s = 0; s < 4; s++) {
                uint2 b = bl[((wk * 4 + s) * 8 + nt) * 32 + lane];
                hmma(acck[0], ah[0][s], b);
                hmma(acck[1], ah[1][s], b);
            }
            acc[0][nt][0] += e00 * acck[0][0];
            acc[0][nt][1] += e00 * acck[0][1];
            acc[0][nt][2] += e01 * acck[0][2];
            acc[0][nt][3] += e01 * acck[0][3];
            acc[1][nt][0] += e10 * acck[1][0];
            acc[1][nt][1] += e10 * acck[1][1];
            acc[1][nt][2] += e11 * acck[1][2];
            acc[1][nt][3] += e11 * acck[1][3];
        }

        if (k + 2 < 8) {
            __syncthreads();   // all warps done with slot before overwrite
            uint2* dst = reinterpret_cast<uint2*>(smb + slot * 32768);
            const uint2* src = wp + (k + 2) * 4096;
            for (int i = 0; i < 8; i++) cp_async16(dst + (i * 256 + t) * 2, src + (i * 256 + t) * 2);
            CP_COMMIT();
        }
    }

    // ---- cross-warp K reduction (wk=1 -> smem staging -> wk=0 adds) ----
    // staging reuses B ring slot-0 region (32KB), transposed conflict-free layout:
    // stg[elem * 128 + (wm*32 + lane)], elem = m*32 + nt*4 + i  (64 elems)
    float* stg = reinterpret_cast<float*>(smb);
    if (wk == 1) {
#pragma unroll
        for (int m = 0; m < 2; m++)
#pragma unroll
            for (int nt = 0; nt < 8; nt++)
#pragma unroll
                for (int i = 0; i < 4; i++)
                    stg[(m * 32 + nt * 4 + i) * 128 + wm * 32 + lane] = acc[m][nt][i];
    }
    __syncthreads();

    if (wk == 0) {
#pragma unroll
        for (int m = 0; m < 2; m++)
#pragma unroll
            for (int nt = 0; nt < 8; nt++)
#pragma unroll
                for (int i = 0; i < 4; i++)
                    acc[m][nt][i] += stg[(m * 32 + nt * 4 + i) * 128 + wm * 32 + lane];

        // ---- epilogue: h = relu(acc + h), in-place (CTA owns its rows) ----
#pragma unroll
        for (int m = 0; m < 2; m++) {
            int gn0 = n0 + fr0 + m * 16;
            int gn1 = gn0 + 8;
#pragma unroll
            for (int nt = 0; nt < 8; nt++) {
                int c = nt * 8 + tig * 2;
                if (gn0 < NN) {
                    float2 hv = *reinterpret_cast<const float2*>(&g_h[gn0 * 64 + c]);
                    float2 o;
                    o.x = fmaxf(acc[m][nt][0] + hv.x, 0.f);
                    o.y = fmaxf(acc[m][nt][1] + hv.y, 0.f);
                    *reinterpret_cast<float2*>(&g_h[gn0 * 64 + c]) = o;
                }
                if (gn1 < NN) {
                    float2 hv = *reinterpret_cast<const float2*>(&g_h[gn1 * 64 + c]);
                    float2 o;
                    o.x = fmaxf(acc[m][nt][2] + hv.x, 0.f);
                    o.y = fmaxf(acc[m][nt][3] + hv.y, 0.f);
                    *reinterpret_cast<float2*>(&g_h[gn1 * 64 + c]) = o;
                }
            }
        }
    }
}

// ---------------- fc1 ----------------
__global__ void __launch_bounds__(256) fc1_kernel(const float* __restrict__ w,
                                                  const float* __restrict__ b,
                                                  float* __restrict__ out) {
    __shared__ float s_w[64 * 16];
    __shared__ float s_b[16];
    int t = threadIdx.x;
    for (int idx = t; idx < 64 * 16; idx += 256) s_w[idx] = w[idx];
    if (t < 16) s_b[t] = b[t];
    __syncthreads();
    int n = blockIdx.x * 256 + t;
    if (n < NN) {
        float hr[64];
#pragma unroll
        for (int i = 0; i < 16; i++) {
            float4 v = *reinterpret_cast<const float4*>(&g_h[n * 64 + i * 4]);
            hr[4 * i] = v.x; hr[4 * i + 1] = v.y; hr[4 * i + 2] = v.z; hr[4 * i + 3] = v.w;
        }
        float o[16];
#pragma unroll
        for (int c = 0; c < 16; c++) {
            float s = s_b[c];
#pragma unroll
            for (int f = 0; f < 64; f++) s += hr[f] * s_w[f * 16 + c];
            o[c] = s;
        }
#pragma unroll
        for (int i = 0; i < 4; i++) {
            *reinterpret_cast<float4*>(&out[n * 16 + i * 4]) =
                make_float4(o[4 * i], o[4 * i + 1], o[4 * i + 2], o[4 * i + 3]);
        }
    }
}

// ---------------- launch ----------------
extern "C" void kernel_launch(void* const* d_in, const int* in_sizes, int n_in,
                              void* d_out, int out_size) {
    const float* x     = (const float*)d_in[0];
    const int*   ei    = (const int*)  d_in[1];
    const float* fc0w  = (const float*)d_in[2];
    const float* fc0b  = (const float*)d_in[3];
    const float* fc1w  = (const float*)d_in[4];
    const float* fc1b  = (const float*)d_in[5];
    const float* envw  = (const float*)d_in[6];
    const float* envb  = (const float*)d_in[7];
    const float* convw = (const float*)d_in[8];
    float* out = (float*)d_out;

    const int* row = ei;
    const int* col = ei + EE;

    cudaFuncSetAttribute(fc0_mma_kernel, cudaFuncAttributeMaxDynamicSharedMemorySize, FC0_SMEM);
    cudaFuncSetAttribute(conv_mma_kernel, cudaFuncAttributeMaxDynamicSharedMemorySize, CONV_SMEM);

    const int nscan = (NN + 1023) / 1024;   // 98

    // CSR build (edges fixed across layers)
    zero_deg_kernel<<<(NN + 255) / 256, 256>>>();
    deg_kernel<<<(EE + 255) / 256, 256>>>(col);
    dn_kernel<<<(NN + 255) / 256, 256>>>();
    scan_block_kernel<<<nscan, 1024>>>();
    scan_bsum_kernel<<<1, 128>>>(nscan);
    scan_add_kernel<<<nscan, 1024>>>();
    fill_csr_kernel<<<(EE + 255) / 256, 256>>>(row, col);

    // pre-packed bf16 hi/lo B fragments
    wpack_kernel<<<48, 256>>>(convw);
    wpack0_kernel<<<2, 256>>>(fc0w);

    fc0_mma_kernel<<<(NN + 127) / 128, 256, FC0_SMEM>>>(x, fc0b);

    for (int i = 0; i < LL; i++) {
        gather_kernel<<<(NN + 15) / 16, 256>>>();
        conv_mma_kernel<<<(NN + 127) / 128, 256, CONV_SMEM>>>(
            envw + i * 2 * HH * KK, envb + i * KK, i);
    }

    fc1_kernel<<<(NN + 255) / 256, 256>>>(fc1w, fc1b, out);
}